// round 2
// baseline (speedup 1.0000x reference)
#include <cuda_runtime.h>
#include <cstdint>

// out = softmax(x @ Wq1, axis over s), where Wq1[d][h] = sum_d' W[d, h*D+d'] * q[h,d'].
// The DeepSets MLP / set_feat / Wb terms are constant over the softmax axis and cancel.

#define B 4
#define N 64
#define S 512
#define D 128
#define H 8
#define SPAD 520  // 520 % 32 == 8 -> (8h + s) distinct banks in the write pass

__device__ float g_wq[H * D];  // layout [h][d]

// ---------------------------------------------------------------------------
// Kernel 1: Wq1[h][d] = sum_j W[d*1024 + h*128 + j] * q[h*128 + j]
// one warp per (d,h) pair; 1024 pairs -> 128 blocks x 256 threads
// ---------------------------------------------------------------------------
__global__ void wq_kernel(const float* __restrict__ W, const float* __restrict__ q) {
    int gwarp = (blockIdx.x * blockDim.x + threadIdx.x) >> 5;
    int lane  = threadIdx.x & 31;
    if (gwarp >= D * H) return;
    int d = gwarp >> 3;
    int h = gwarp & 7;
    const float4* wrow = reinterpret_cast<const float4*>(W + (size_t)d * (H * D) + h * D);
    const float4* qrow = reinterpret_cast<const float4*>(q + h * D);
    float4 wv = wrow[lane];
    float4 qv = qrow[lane];
    float p = wv.x * qv.x + wv.y * qv.y + wv.z * qv.z + wv.w * qv.w;
    #pragma unroll
    for (int off = 16; off; off >>= 1) p += __shfl_xor_sync(0xFFFFFFFFu, p, off);
    if (lane == 0) g_wq[h * D + d] = p;
}

// ---------------------------------------------------------------------------
// Kernel 2: per (b,n) block: e[s][h] = x[s,:] . Wq1[:,h]; softmax over s; write.
// ---------------------------------------------------------------------------
__global__ __launch_bounds__(256) void attn_kernel(const float* __restrict__ x,
                                                   float* __restrict__ out) {
    __shared__ float esm[H * SPAD];
    __shared__ float s_inv[H];

    const int bn   = blockIdx.x;       // 0..255  == b*N + n
    const int tid  = threadIdx.x;
    const int warp = tid >> 5;
    const int lane = tid & 31;

    // Each lane caches Wq1 for dims [4*lane, 4*lane+4), all 8 heads (32 regs).
    float4 wq4[H];
    #pragma unroll
    for (int h = 0; h < H; h++)
        wq4[h] = *reinterpret_cast<const float4*>(g_wq + h * D + lane * 4);

    const float4* xb = reinterpret_cast<const float4*>(x + (size_t)bn * S * D);

    // head owned by this lane after the reduce-scatter
    const int h_lane = ((lane >> 4) & 1) * 4 + ((lane >> 3) & 1) * 2 + ((lane >> 2) & 1);
    const bool hi = (lane & 16) != 0;
    const bool b8 = (lane & 8) != 0;
    const bool b4 = (lane & 4) != 0;

    // Warp handles rows [warp*64, warp*64+64). Batch 4 loads for MLP.
    for (int i0 = 0; i0 < 64; i0 += 4) {
        float4 xv[4];
        #pragma unroll
        for (int k = 0; k < 4; k++)
            xv[k] = xb[(size_t)(warp * 64 + i0 + k) * 32 + lane];

        #pragma unroll
        for (int k = 0; k < 4; k++) {
            const int s = warp * 64 + i0 + k;
            float p[H];
            #pragma unroll
            for (int h = 0; h < H; h++) {
                p[h] = fmaf(xv[k].x, wq4[h].x,
                       fmaf(xv[k].y, wq4[h].y,
                       fmaf(xv[k].z, wq4[h].z, xv[k].w * wq4[h].w)));
            }
            // reduce-scatter: 16 shuffles instead of 40
            // stage A (xor 16): keep 4 heads
            float q4[4];
            #pragma unroll
            for (int i = 0; i < 8; i++) {
                float t = __shfl_xor_sync(0xFFFFFFFFu, p[i], 16);
                if (hi) { if (i >= 4) q4[i - 4] = p[i] + t; }
                else    { if (i <  4) q4[i]     = p[i] + t; }
            }
            // stage B (xor 8): keep 2
            float r2[2];
            #pragma unroll
            for (int i = 0; i < 4; i++) {
                float t = __shfl_xor_sync(0xFFFFFFFFu, q4[i], 8);
                if (b8) { if (i >= 2) r2[i - 2] = q4[i] + t; }
                else    { if (i <  2) r2[i]     = q4[i] + t; }
            }
            // stage C (xor 4): keep 1
            float t0 = __shfl_xor_sync(0xFFFFFFFFu, r2[0], 4);
            float t1 = __shfl_xor_sync(0xFFFFFFFFu, r2[1], 4);
            float s1 = b4 ? (r2[1] + t1) : (r2[0] + t0);
            // stage D: full sum within 4-lane group
            s1 += __shfl_xor_sync(0xFFFFFFFFu, s1, 2);
            s1 += __shfl_xor_sync(0xFFFFFFFFu, s1, 1);

            if ((lane & 3) == 0) esm[h_lane * SPAD + s] = s1;
        }
    }
    __syncthreads();

    // Softmax over s, one warp per head.
    {
        const int h = warp;
        float vals[16];
        float m = -1e30f;
        #pragma unroll
        for (int i = 0; i < 16; i++) {
            vals[i] = esm[h * SPAD + i * 32 + lane];
            m = fmaxf(m, vals[i]);
        }
        #pragma unroll
        for (int off = 16; off; off >>= 1)
            m = fmaxf(m, __shfl_xor_sync(0xFFFFFFFFu, m, off));
        float sum = 0.0f;
        #pragma unroll
        for (int i = 0; i < 16; i++) {
            float t = __expf(vals[i] - m);
            esm[h * SPAD + i * 32 + lane] = t;
            sum += t;
        }
        #pragma unroll
        for (int off = 16; off; off >>= 1)
            sum += __shfl_xor_sync(0xFFFFFFFFu, sum, off);
        if (lane == 0) s_inv[h] = 1.0f / sum;
    }
    __syncthreads();

    // Coalesced normalized write: out[b,n,s,h]
    float* ob = out + (size_t)bn * (S * H);
    #pragma unroll
    for (int idx = tid; idx < S * H; idx += 256) {
        int s = idx >> 3;
        int h = idx & 7;
        ob[idx] = esm[h * SPAD + s] * s_inv[h];
    }
}

extern "C" void kernel_launch(void* const* d_in, const int* in_sizes, int n_in,
                              void* d_out, int out_size) {
    // metadata order: x, w1, b1, w2, b2, w3, b3, W, Wb, q
    const float* x = (const float*)d_in[0];
    const float* W = (const float*)d_in[7];
    const float* q = (const float*)d_in[9];
    float* out = (float*)d_out;

    wq_kernel<<<128, 256>>>(W, q);           // 1024 warps -> 1024 (d,h) dots
    attn_kernel<<<B * N, 256>>>(x, out);     // 256 blocks
}

// round 3
// speedup vs baseline: 1.0014x; 1.0014x over previous
#include <cuda_runtime.h>
#include <cstdint>

// out = softmax(x @ Wq1, axis over s), Wq1[h][d] = sum_j W[d, h*D+j] * q[h,j].
// DeepSets MLP / set_feat / Wb are constant over the softmax axis and cancel.

#define B 4
#define N 64
#define S 512
#define D 128
#define H 8

__device__ float g_wq[H * D];          // [h][d]
__device__ float g_e[B * N * H * S];   // [bn][h][s]  (4 MB scratch)

// ---------------------------------------------------------------------------
// Kernel 1: Wq1[h][d] = sum_j W[d*1024 + h*128 + j] * q[h*128 + j]
// one warp per (d,h); 1024 warps
// ---------------------------------------------------------------------------
__global__ void wq_kernel(const float* __restrict__ W, const float* __restrict__ q) {
    int gwarp = (blockIdx.x * blockDim.x + threadIdx.x) >> 5;
    int lane  = threadIdx.x & 31;
    if (gwarp >= D * H) return;
    int d = gwarp >> 3;
    int h = gwarp & 7;
    const float4* wrow = reinterpret_cast<const float4*>(W + (size_t)d * (H * D) + h * D);
    const float4* qrow = reinterpret_cast<const float4*>(q + h * D);
    float4 wv = wrow[lane];
    float4 qv = qrow[lane];
    float p = wv.x * qv.x + wv.y * qv.y + wv.z * qv.z + wv.w * qv.w;
    #pragma unroll
    for (int off = 16; off; off >>= 1) p += __shfl_xor_sync(0xFFFFFFFFu, p, off);
    if (lane == 0) g_wq[h * D + d] = p;
}

// ---------------------------------------------------------------------------
// Kernel 2: streaming e-compute. CTA = 128 rows of one (b,n); 1024 CTAs,
// 128 threads (4 warps x 32 rows). One launch wave at 8 CTAs/SM.
// ---------------------------------------------------------------------------
__global__ __launch_bounds__(128, 8) void ecompute(const float* __restrict__ x) {
    __shared__ float es[H][132];   // 132 % 32 == 4 -> scatter stores conflict-free

    const int blk   = blockIdx.x;
    const int bn    = blk >> 2;
    const int chunk = blk & 3;
    const int tid   = threadIdx.x;
    const int warp  = tid >> 5;
    const int lane  = tid & 31;

    // lane caches Wq1 for dims [4*lane, 4*lane+4), all heads (32 regs)
    float4 wq4[H];
    #pragma unroll
    for (int h = 0; h < H; h++)
        wq4[h] = *reinterpret_cast<const float4*>(g_wq + h * D + lane * 4);

    const float4* xb = reinterpret_cast<const float4*>(x)
                     + ((size_t)bn * S + chunk * 128) * 32;

    const int h_lane = ((lane >> 4) & 1) * 4 + ((lane >> 3) & 1) * 2 + ((lane >> 2) & 1);
    const bool hi = (lane & 16) != 0;
    const bool b8 = (lane & 8) != 0;
    const bool b4 = (lane & 4) != 0;

    // warp handles rows [warp*32, warp*32+32), batched 4 deep
    for (int i0 = 0; i0 < 32; i0 += 4) {
        float4 xv[4];
        #pragma unroll
        for (int k = 0; k < 4; k++)
            xv[k] = xb[(size_t)(warp * 32 + i0 + k) * 32 + lane];

        #pragma unroll
        for (int k = 0; k < 4; k++) {
            const int r = warp * 32 + i0 + k;
            float p[H];
            #pragma unroll
            for (int h = 0; h < H; h++) {
                p[h] = fmaf(xv[k].x, wq4[h].x,
                       fmaf(xv[k].y, wq4[h].y,
                       fmaf(xv[k].z, wq4[h].z, xv[k].w * wq4[h].w)));
            }
            // reduce-scatter across lanes: 16 shuffles
            float q4[4];
            #pragma unroll
            for (int i = 0; i < 8; i++) {
                float t = __shfl_xor_sync(0xFFFFFFFFu, p[i], 16);
                if (hi) { if (i >= 4) q4[i - 4] = p[i] + t; }
                else    { if (i <  4) q4[i]     = p[i] + t; }
            }
            float r2[2];
            #pragma unroll
            for (int i = 0; i < 4; i++) {
                float t = __shfl_xor_sync(0xFFFFFFFFu, q4[i], 8);
                if (b8) { if (i >= 2) r2[i - 2] = q4[i] + t; }
                else    { if (i <  2) r2[i]     = q4[i] + t; }
            }
            float t0 = __shfl_xor_sync(0xFFFFFFFFu, r2[0], 4);
            float t1 = __shfl_xor_sync(0xFFFFFFFFu, r2[1], 4);
            float s1 = b4 ? (r2[1] + t1) : (r2[0] + t0);
            s1 += __shfl_xor_sync(0xFFFFFFFFu, s1, 2);
            s1 += __shfl_xor_sync(0xFFFFFFFFu, s1, 1);

            if ((lane & 3) == 0) es[h_lane][r] = s1;
        }
    }
    __syncthreads();

    // coalesced write: g_e[bn][h][chunk*128 + t]
    float* ge = g_e + (size_t)bn * (H * S) + chunk * 128;
    #pragma unroll
    for (int h = 0; h < H; h++)
        ge[h * S + tid] = es[h][tid];
}

// ---------------------------------------------------------------------------
// Kernel 3: softmax over s per (bn, h) + transposed coalesced write.
// ---------------------------------------------------------------------------
#define SP 516   // 516 % 32 == 4 -> write-pass banks (4h + s) all distinct

__global__ __launch_bounds__(256) void softmax_kernel(float* __restrict__ out) {
    __shared__ float es[H * SP];
    __shared__ float s_inv[H];

    const int bn   = blockIdx.x;
    const int tid  = threadIdx.x;
    const int warp = tid >> 5;
    const int lane = tid & 31;

    const float* ge = g_e + (size_t)bn * (H * S);
    #pragma unroll
    for (int idx = tid; idx < H * S; idx += 256)
        es[(idx >> 9) * SP + (idx & 511)] = ge[idx];
    __syncthreads();

    // warp per head
    {
        const int h = warp;
        float vals[16];
        float m = -1e30f;
        #pragma unroll
        for (int i = 0; i < 16; i++) {
            vals[i] = es[h * SP + i * 32 + lane];
            m = fmaxf(m, vals[i]);
        }
        #pragma unroll
        for (int off = 16; off; off >>= 1)
            m = fmaxf(m, __shfl_xor_sync(0xFFFFFFFFu, m, off));
        float sum = 0.0f;
        #pragma unroll
        for (int i = 0; i < 16; i++) {
            float t = __expf(vals[i] - m);
            es[h * SP + i * 32 + lane] = t;
            sum += t;
        }
        #pragma unroll
        for (int off = 16; off; off >>= 1)
            sum += __shfl_xor_sync(0xFFFFFFFFu, sum, off);
        if (lane == 0) s_inv[h] = 1.0f / sum;
    }
    __syncthreads();

    // coalesced transposed write: out[bn][s][h]
    float* ob = out + (size_t)bn * (S * H);
    #pragma unroll
    for (int idx = tid; idx < S * H; idx += 256) {
        int s = idx >> 3;
        int h = idx & 7;
        ob[idx] = es[h * SP + s] * s_inv[h];
    }
}

extern "C" void kernel_launch(void* const* d_in, const int* in_sizes, int n_in,
                              void* d_out, int out_size) {
    // metadata order: x, w1, b1, w2, b2, w3, b3, W, Wb, q
    const float* x = (const float*)d_in[0];
    const float* W = (const float*)d_in[7];
    const float* q = (const float*)d_in[9];
    float* out = (float*)d_out;

    wq_kernel<<<128, 256>>>(W, q);
    ecompute<<<B * N * 4, 128>>>(x);
    softmax_kernel<<<B * N, 256>>>(out);
}